// round 11
// baseline (speedup 1.0000x reference)
#include <cuda_runtime.h>
#include <cuda_bf16.h>
#include <cstdint>

// Problem constants
#define Bsz 8192
#define Din 1024
#define Rk  64

// ---------------------------------------------------------------------------
// Scratch (__device__ globals; cudaMalloc forbidden)
// ---------------------------------------------------------------------------
__device__ float g_u[Bsz * Rk];          // 2 MB   (written by apg_mma)
__device__ float g_h[Bsz * Rk];          // 2 MB
__device__ float g_act0[Bsz * Din];      // 32 MB
__device__ float g_act1[Bsz * Din];      // 32 MB
__device__ float g_Vx[Din * 128];        // 512 KB  [V | (bm@V^T)^T]
// bf16 hi/lo planes
__device__ __align__(16) __nv_bfloat16 g_Ah[(size_t)Bsz * Din];   // 16 MB
__device__ __align__(16) __nv_bfloat16 g_Al[(size_t)Bsz * Din];   // 16 MB
__device__ __align__(16) __nv_bfloat16 g_Bh[(size_t)4096 * Din];  // 8 MB
__device__ __align__(16) __nv_bfloat16 g_Bl[(size_t)4096 * Din];  // 8 MB
__device__ __align__(16) __nv_bfloat16 g_Uh[(size_t)Rk * Din];    // 128 KB
__device__ __align__(16) __nv_bfloat16 g_Ul[(size_t)Rk * Din];    // 128 KB

__device__ __forceinline__ const float* in_sel(const float* ext, int sel) {
    if (sel == 0) return g_act0;
    if (sel == 1) return g_act1;
    return ext;
}
__device__ __forceinline__ float* out_sel(float* ext, int sel) {
    if (sel == 0) return g_act0;
    if (sel == 1) return g_act1;
    return ext;
}

// ---------------------------------------------------------------------------
// PTX helpers (baseline PTX only — harness targets plain sm_103)
// ---------------------------------------------------------------------------
__device__ __forceinline__ uint32_t smem_u32(const void* p) {
    uint32_t a;
    asm("{ .reg .u64 t; cvta.to.shared.u64 t, %1; cvt.u32.u64 %0, t; }"
        : "=r"(a) : "l"(p));
    return a;
}
#define CPASYNC16(saddr, gptr) \
    asm volatile("cp.async.cg.shared.global [%0], [%1], 16;" \
                 :: "r"(saddr), "l"(gptr) : "memory")
#define CP_COMMIT() asm volatile("cp.async.commit_group;" ::: "memory")
#define CP_WAIT1()  asm volatile("cp.async.wait_group 1;" ::: "memory")

#define LDM4(r, addr) \
    asm volatile("ldmatrix.sync.aligned.m8n8.x4.shared.b16 {%0,%1,%2,%3}, [%4];" \
                 : "=r"((r)[0]), "=r"((r)[1]), "=r"((r)[2]), "=r"((r)[3]) \
                 : "r"(addr))
#define LDM2(r, addr) \
    asm volatile("ldmatrix.sync.aligned.m8n8.x2.shared.b16 {%0,%1}, [%2];" \
                 : "=r"((r)[0]), "=r"((r)[1]) \
                 : "r"(addr))

#define MMA16816(d, a, b) \
    asm volatile("mma.sync.aligned.m16n8k16.row.col.f32.bf16.bf16.f32 " \
                 "{%0,%1,%2,%3}, {%4,%5,%6,%7}, {%8,%9}, {%0,%1,%2,%3};" \
                 : "+f"((d)[0]), "+f"((d)[1]), "+f"((d)[2]), "+f"((d)[3]) \
                 : "r"((a)[0]), "r"((a)[1]), "r"((a)[2]), "r"((a)[3]), \
                   "r"((b)[0]), "r"((b)[1]))

// ---------------------------------------------------------------------------
// Shared-memory layout of the MMA kernel (bytes). Pitch 144 B.
// B region holds 136 rows: 0-127 = Wm tile, 128-129 = the CTA's two U rows
// (u fused as 2 extra output columns), 130-135 = don't-care.
// ---------------------------------------------------------------------------
#define ST_A_H   0               // 256 x 144 = 36864
#define ST_A_L   36864
#define ST_B_H   73728           // 136 x 144 = 19584
#define ST_B_L   93312
#define ST_BYTES 112896          // one stage
#define OFF_UF   225792          // u staging: 512 floats = 2048 B
#define SMEM_MMA 227840

// ---------------------------------------------------------------------------
// zero g_h only (g_u is fully overwritten by apg_mma)
// ---------------------------------------------------------------------------
__global__ void zero_kernel() {
    int i = blockIdx.x * 256 + threadIdx.x;   // 131072 float4
    reinterpret_cast<float4*>(g_h)[i] = make_float4(0.f, 0.f, 0.f, 0.f);
}

// ---------------------------------------------------------------------------
// g_Vx[o][0:64] = V[o][:],  g_Vx[o][64+r] = sum_s bm[r*64+s] * V[o][s]
// ---------------------------------------------------------------------------
__global__ __launch_bounds__(128)
void w2v_kernel(const float* __restrict__ V, const float* __restrict__ bm) {
    __shared__ float Vrow[64];
    __shared__ float bms[4096];
    const int o = blockIdx.x, t = threadIdx.x;
    for (int j = t; j < 4096; j += 128) bms[j] = bm[j];
    if (t < 64) Vrow[t] = V[o * 64 + t];
    __syncthreads();
    if (t < 64) {
        g_Vx[o * 128 + t] = Vrow[t];
    } else {
        const int r = t - 64;
        float s = 0.f;
#pragma unroll
        for (int ss = 0; ss < 64; ++ss) s = fmaf(bms[r * 64 + ss], Vrow[ss], s);
        g_Vx[o * 128 + 64 + r] = s;
    }
}

// ---------------------------------------------------------------------------
// Conversion: fp32 -> bf16 hi/lo planes (elementwise). dst: 0=A, 1=B, 2=U.
// ---------------------------------------------------------------------------
__global__ __launch_bounds__(256)
void conv_kernel(const float* __restrict__ Sext, int sel, int dst) {
    const float* S = in_sel(Sext, sel);
    __nv_bfloat16* H = (dst == 0) ? g_Ah : (dst == 1) ? g_Bh : g_Uh;
    __nv_bfloat16* L = (dst == 0) ? g_Al : (dst == 1) ? g_Bl : g_Ul;
    size_t i4 = (size_t)blockIdx.x * 256 + threadIdx.x;
    float4 v = reinterpret_cast<const float4*>(S)[i4];
    __nv_bfloat16 h0 = __float2bfloat16_rn(v.x), h1 = __float2bfloat16_rn(v.y);
    __nv_bfloat16 h2 = __float2bfloat16_rn(v.z), h3 = __float2bfloat16_rn(v.w);
    __nv_bfloat162 lo01 = __floats2bfloat162_rn(v.x - __bfloat162float(h0),
                                                v.y - __bfloat162float(h1));
    __nv_bfloat162 lo23 = __floats2bfloat162_rn(v.z - __bfloat162float(h2),
                                                v.w - __bfloat162float(h3));
    uint2 hp, lp;
    hp.x = (uint32_t)__bfloat16_as_ushort(h0) | ((uint32_t)__bfloat16_as_ushort(h1) << 16);
    hp.y = (uint32_t)__bfloat16_as_ushort(h2) | ((uint32_t)__bfloat16_as_ushort(h3) << 16);
    lp.x = *reinterpret_cast<uint32_t*>(&lo01);
    lp.y = *reinterpret_cast<uint32_t*>(&lo23);
    *reinterpret_cast<uint2*>(H + 4 * i4) = hp;
    *reinterpret_cast<uint2*>(L + 4 * i4) = lp;
}

// ---------------------------------------------------------------------------
// Main GEMM: C = X @ Wm^T (bf16 3-term HMMA) + fused u (2 extra B cols)
// + fused einsum epilogue.  CTA M=256 x N=128(+2), 512 threads,
// warp grid 4x4 (warp tile 64x32); warps with mw==nw also compute u.
// k-chunk 64, 2-stage cp.async pipeline. grid = (32 nb, 32 mb).
// ---------------------------------------------------------------------------
__global__ __launch_bounds__(512, 1)
void apg_mma_kernel() {
    extern __shared__ __align__(16) char sm[];
    const int t = threadIdx.x, lane = t & 31, w = t >> 5;
    const int mw = w >> 2, nw = w & 3;
    const int nb = blockIdx.x, mb = blockIdx.y;
    const int m0 = mb * 256, n0 = nb * 128;
    const uint32_t smb = smem_u32(sm);

    const __nv_bfloat16* gAh = g_Ah + (size_t)m0 * Din;
    const __nv_bfloat16* gAl = g_Al + (size_t)m0 * Din;
    const __nv_bfloat16* gBh = g_Bh + (size_t)n0 * Din;
    const __nv_bfloat16* gBl = g_Bl + (size_t)n0 * Din;
    const __nv_bfloat16* gUh = g_Uh + (size_t)(2 * nb) * Din;
    const __nv_bfloat16* gUl = g_Ul + (size_t)(2 * nb) * Din;

    auto issue = [&](int kc, int stg) {
        uint32_t sb0 = smb + stg * ST_BYTES;
        const size_t ko = (size_t)kc * 64;
#pragma unroll
        for (int i = 0; i < 4; ++i) {
            int idx = t + i * 512, row = idx >> 3, grp = idx & 7;
            CPASYNC16(sb0 + ST_A_H + row * 144 + grp * 16, gAh + (size_t)row * Din + ko + grp * 8);
            CPASYNC16(sb0 + ST_A_L + row * 144 + grp * 16, gAl + (size_t)row * Din + ko + grp * 8);
        }
#pragma unroll
        for (int i = 0; i < 2; ++i) {
            int idx = t + i * 512, row = idx >> 3, grp = idx & 7;
            CPASYNC16(sb0 + ST_B_H + row * 144 + grp * 16, gBh + (size_t)row * Din + ko + grp * 8);
            CPASYNC16(sb0 + ST_B_L + row * 144 + grp * 16, gBl + (size_t)row * Din + ko + grp * 8);
        }
        // the CTA's two U rows -> B rows 128,129 (both planes)
        if (t < 32) {
            int plane = t >> 4, row = (t >> 3) & 1, grp = t & 7;
            const __nv_bfloat16* su = (plane ? gUl : gUh) + (size_t)row * Din + ko + grp * 8;
            uint32_t du = sb0 + (plane ? ST_B_L : ST_B_H) + (128 + row) * 144 + grp * 16;
            CPASYNC16(du, su);
        }
    };

    issue(0, 0);
    CP_COMMIT();

    float acc[4][4][4];
#pragma unroll
    for (int i = 0; i < 4; ++i)
#pragma unroll
        for (int j = 0; j < 4; ++j)
#pragma unroll
            for (int e = 0; e < 4; ++e) acc[i][j][e] = 0.f;
    float uacc[4][4];
#pragma unroll
    for (int i = 0; i < 4; ++i)
#pragma unroll
        for (int e = 0; e < 4; ++e) uacc[i][e] = 0.f;

    const bool uwarp = (mw == nw);
    const int arow = lane & 15, acol = (lane >> 4) * 8;
    const int brow = ((lane >> 4) << 3) + (lane & 7), bcol = ((lane >> 3) & 1) * 8;
    const uint32_t aoff = ((mw * 64 + arow) * 72 + acol) * 2;
    const uint32_t boff = ((nw * 32 + brow) * 72 + bcol) * 2;
    const uint32_t uoff = (128 + (lane & 7)) * 144 + ((lane >> 3) & 1) * 16;

    for (int i = 0; i < 16; ++i) {
        if (i < 15) issue(i + 1, (i + 1) & 1);
        CP_COMMIT();
        CP_WAIT1();
        __syncthreads();                       // chunk i staged

        const uint32_t base = smb + (i & 1) * ST_BYTES;
#pragma unroll
        for (int ks = 0; ks < 4; ++ks) {
            uint32_t ah[4][4], al[4][4];
#pragma unroll
            for (int mt = 0; mt < 4; ++mt) {
                uint32_t aa = base + ST_A_H + aoff + mt * (16 * 144) + ks * 32;
                LDM4(ah[mt], aa);
                LDM4(al[mt], aa + (ST_A_L - ST_A_H));
            }
#pragma unroll
            for (int p = 0; p < 2; ++p) {
                uint32_t bb = base + ST_B_H + boff + p * (16 * 144) + ks * 32;
                uint32_t bh4[4], bl4[4];
                LDM4(bh4, bb);
                LDM4(bl4, bb + (ST_B_L - ST_B_H));
                uint32_t b0h[2] = {bh4[0], bh4[1]}, b1h[2] = {bh4[2], bh4[3]};
                uint32_t b0l[2] = {bl4[0], bl4[1]}, b1l[2] = {bl4[2], bl4[3]};
#pragma unroll
                for (int mt = 0; mt < 4; ++mt) {
                    MMA16816(acc[mt][2 * p], ah[mt], b0h);
                    MMA16816(acc[mt][2 * p], ah[mt], b0l);
                    MMA16816(acc[mt][2 * p], al[mt], b0h);
                    MMA16816(acc[mt][2 * p + 1], ah[mt], b1h);
                    MMA16816(acc[mt][2 * p + 1], ah[mt], b1l);
                    MMA16816(acc[mt][2 * p + 1], al[mt], b1h);
                }
            }
            if (uwarp) {
                uint32_t buh[2], bul[2];
                LDM2(buh, base + ST_B_H + uoff + ks * 32);
                LDM2(bul, base + ST_B_L + uoff + ks * 32);
#pragma unroll
                for (int mt = 0; mt < 4; ++mt) {
                    MMA16816(uacc[mt], ah[mt], buh);
                    MMA16816(uacc[mt], ah[mt], bul);
                    MMA16816(uacc[mt], al[mt], buh);
                }
            }
        }
        __syncthreads();                       // all warps done with stage i&1
    }

    // ---- u: cols 128,129 live at lanes with (lane&3)==0, regs [0],[1] ----
    float* uf = reinterpret_cast<float*>(sm + OFF_UF);
    if (uwarp && (lane & 3) == 0) {
#pragma unroll
        for (int mt = 0; mt < 4; ++mt) {
            int mr = mw * 64 + mt * 16 + (lane >> 2);
            uf[mr * 2 + 0] = uacc[mt][0];
            uf[mr * 2 + 1] = uacc[mt][1];
            uf[(mr + 8) * 2 + 0] = uacc[mt][2];
            uf[(mr + 8) * 2 + 1] = uacc[mt][3];
            g_u[(size_t)(m0 + mr) * Rk + 2 * nb + 0] = uacc[mt][0];
            g_u[(size_t)(m0 + mr) * Rk + 2 * nb + 1] = uacc[mt][1];
            g_u[(size_t)(m0 + mr + 8) * Rk + 2 * nb + 0] = uacc[mt][2];
            g_u[(size_t)(m0 + mr + 8) * Rk + 2 * nb + 1] = uacc[mt][3];
        }
    }
    __syncthreads();

    // ---- fused einsum epilogue ----
    float* hp = reinterpret_cast<float*>(sm);              // 256 x 65 floats
    const int mbase = mw * 64, scol = (nw & 1) * 32;
    if (nw < 2) {    // cols 0..63 -> r = 2nb (u0)
#pragma unroll
        for (int mt = 0; mt < 4; ++mt)
#pragma unroll
            for (int nt = 0; nt < 4; ++nt) {
                int m0r = mbase + mt * 16 + (lane >> 2);
                int s0 = scol + nt * 8 + 2 * (lane & 3);
                hp[m0r * 65 + s0]           = acc[mt][nt][0] * uf[m0r * 2];
                hp[m0r * 65 + s0 + 1]       = acc[mt][nt][1] * uf[m0r * 2];
                hp[(m0r + 8) * 65 + s0]     = acc[mt][nt][2] * uf[(m0r + 8) * 2];
                hp[(m0r + 8) * 65 + s0 + 1] = acc[mt][nt][3] * uf[(m0r + 8) * 2];
            }
    }
    __syncthreads();
    if (nw >= 2) {   // cols 64..127 -> r = 2nb+1 (u1)
#pragma unroll
        for (int mt = 0; mt < 4; ++mt)
#pragma unroll
            for (int nt = 0; nt < 4; ++nt) {
                int m0r = mbase + mt * 16 + (lane >> 2);
                int s0 = scol + nt * 8 + 2 * (lane & 3);
                hp[m0r * 65 + s0]           += acc[mt][nt][0] * uf[m0r * 2 + 1];
                hp[m0r * 65 + s0 + 1]       += acc[mt][nt][1] * uf[m0r * 2 + 1];
                hp[(m0r + 8) * 65 + s0]     += acc[mt][nt][2] * uf[(m0r + 8) * 2 + 1];
                hp[(m0r + 8) * 65 + s0 + 1] += acc[mt][nt][3] * uf[(m0r + 8) * 2 + 1];
            }
    }
    __syncthreads();

    float* dst = g_h + (size_t)m0 * Rk;
#pragma unroll 8
    for (int ii = 0; ii < 32; ++ii) {
        int idx = ii * 512 + t;               // m = idx>>6, s = idx&63
        atomicAdd(dst + idx, hp[(idx >> 6) * 65 + (idx & 63)]);
    }
}

// ---------------------------------------------------------------------------
// out = [h | u] @ [V | W2]^T + b (+ReLU). Optionally also emits bf16 hi/lo
// planes of the activation (feeds next layer's GEMM).
// K=128. grid (8, 64), 256 thr.
// ---------------------------------------------------------------------------
__global__ __launch_bounds__(256, 2)
void apg_out_kernel(const float* __restrict__ bias,
                    float* __restrict__ Oext, int osel, int relu, int planes) {
    float* O = out_sel(Oext, osel);
    __shared__ float sb[8448];
    const int tid = threadIdx.x;
    const int m0 = blockIdx.y * 128;
    const int n0 = blockIdx.x * 128;
    const int tx = tid & 15, ty = tid >> 4;

    float acc[8][8] = {};
    for (int k0 = 0; k0 < 128; k0 += 32) {
        const float* Asrc = (k0 < 64) ? g_h : g_u;
        const int kk = k0 & 63;
#pragma unroll
        for (int it = 0; it < 4; ++it) {
            int t = tid + it * 256;
            int row = t >> 3, quad = t & 7;
            float4 v = *reinterpret_cast<const float4*>(
                Asrc + (size_t)(m0 + row) * Rk + kk + quad * 4);
            sb[(quad * 4 + 0) * 132 + row] = v.x;
            sb[(quad * 4 + 1) * 132 + row] = v.y;
            sb[(quad * 4 + 2) * 132 + row] = v.z;
            sb[(quad * 4 + 3) * 132 + row] = v.w;
            float4 wv = *reinterpret_cast<const float4*>(
                g_Vx + (size_t)(n0 + row) * 128 + k0 + quad * 4);
            sb[4224 + (quad * 4 + 0) * 132 + row] = wv.x;
            sb[4224 + (quad * 4 + 1) * 132 + row] = wv.y;
            sb[4224 + (quad * 4 + 2) * 132 + row] = wv.z;
            sb[4224 + (quad * 4 + 3) * 132 + row] = wv.w;
        }
        __syncthreads();
#pragma unroll
        for (int k = 0; k < 32; ++k) {
            float a[8], b[8];
            float4 a0 = *reinterpret_cast<const float4*>(sb + k * 132 + ty * 8);
            float4 a1 = *reinterpret_cast<const float4*>(sb + k * 132 + ty * 8 + 4);
            float4 b0 = *reinterpret_cast<const float4*>(sb + 4224 + k * 132 + tx * 8);
            float4 b1 = *reinterpret_cast<const float4*>(sb + 4224 + k * 132 + tx * 8 + 4);
            a[0] = a0.x; a[1] = a0.y; a[2] = a0.z; a[3] = a0.w;
            a[4] = a1.x; a[5] = a1.y; a[6] = a1.z; a[7] = a1.w;
            b[0] = b0.x; b[1] = b0.y; b[2] = b0.z; b[3] = b0.w;
            b[4] = b1.x; b[5] = b1.y; b[6] = b1.z; b[7] = b1.w;
#pragma unroll
            for (int i = 0; i < 8; ++i)
#pragma unroll
                for (int j = 0; j < 8; ++j) acc[i][j] += a[i] * b[j];
        }
        __syncthreads();
    }

    float4 bv0 = *reinterpret_cast<const float4*>(bias + n0 + tx * 8);
    float4 bv1 = *reinterpret_cast<const float4*>(bias + n0 + tx * 8 + 4);
    float bb[8] = {bv0.x, bv0.y, bv0.z, bv0.w, bv1.x, bv1.y, bv1.z, bv1.w};
#pragma unroll
    for (int i = 0; i < 8; ++i) {
        float v[8];
#pragma unroll
        for (int j = 0; j < 8; ++j) {
            v[j] = acc[i][j] + bb[j];
            if (relu) v[j] = fmaxf(v[j], 0.0f);
        }
        size_t base = (size_t)(m0 + ty * 8 + i) * Din + n0 + tx * 8;
        float4* dst = reinterpret_cast<float4*>(O + base);
        dst[0] = make_float4(v[0], v[1], v[2], v[3]);
        dst[1] = make_float4(v[4], v[5], v[6], v[7]);
        if (planes) {
            uint2 hpk[2], lpk[2];
#pragma unroll
            for (int q = 0; q < 2; ++q) {
                __nv_bfloat16 h0 = __float2bfloat16_rn(v[4 * q + 0]);
                __nv_bfloat16 h1 = __float2bfloat16_rn(v[4 * q + 1]);
                __nv_bfloat16 h2 = __float2bfloat16_rn(v[4 * q + 2]);
                __nv_bfloat16 h3 = __float2bfloat16_rn(v[4 * q + 3]);
                __nv_bfloat162 l01 = __floats2bfloat162_rn(
                    v[4 * q + 0] - __bfloat162float(h0),
                    v[4 * q + 1] - __bfloat162float(h1));
                __nv_bfloat162 l23 = __floats2bfloat162_rn(
                    v[4 * q + 2] - __bfloat162float(h2),
                    v[4 * q + 3] - __bfloat162float(h3));
                hpk[q].x = (uint32_t)__bfloat16_as_ushort(h0) |
                           ((uint32_t)__bfloat16_as_ushort(h1) << 16);
                hpk[q].y = (uint32_t)__bfloat16_as_ushort(h2) |
                           ((uint32_t)__bfloat16_as_ushort(h3) << 16);
                lpk[q].x = *reinterpret_cast<uint32_t*>(&l01);
                lpk[q].y = *reinterpret_cast<uint32_t*>(&l23);
            }
            *reinterpret_cast<uint4*>(g_Ah + base) =
                make_uint4(hpk[0].x, hpk[0].y, hpk[1].x, hpk[1].y);
            *reinterpret_cast<uint4*>(g_Al + base) =
                make_uint4(lpk[0].x, lpk[0].y, lpk[1].x, lpk[1].y);
        }
    }
}

// ---------------------------------------------------------------------------
// Launch
// ---------------------------------------------------------------------------
static void run_layer(const float* xext, int xsel, int need_conv,
                      const float* Wm, const float* bm, const float* U,
                      const float* V, const float* bias,
                      float* oext, int osel, int relu, int planes) {
    zero_kernel<<<512, 256>>>();
    w2v_kernel<<<Din, 128>>>(V, bm);
    if (need_conv) conv_kernel<<<8192, 256>>>(xext, xsel, 0);  // x -> A planes
    conv_kernel<<<4096, 256>>>(Wm, 2, 1);                      // Wm -> B planes
    conv_kernel<<<64, 256>>>(U, 2, 2);                         // U  -> U planes
    apg_mma_kernel<<<dim3(32, 32), 512, SMEM_MMA>>>();
    apg_out_kernel<<<dim3(8, 64), 256>>>(bias, oext, osel, relu, planes);
}

extern "C" void kernel_launch(void* const* d_in, const int* in_sizes, int n_in,
                              void* d_out, int out_size) {
    cudaFuncSetAttribute(apg_mma_kernel,
                         cudaFuncAttributeMaxDynamicSharedMemorySize, SMEM_MMA);
    const float* x = (const float*)d_in[0];
    // layer 0: x -> g_act0 (+ planes for layer 1)
    run_layer(x, 2, 1,
              (const float*)d_in[1], (const float*)d_in[2], (const float*)d_in[3],
              (const float*)d_in[4], (const float*)d_in[5],
              nullptr, 0, 1, 1);
    // layer 1: g_act0 -> g_act1 (+ planes for layer 2)
    run_layer(nullptr, 0, 0,
              (const float*)d_in[6], (const float*)d_in[7], (const float*)d_in[8],
              (const float*)d_in[9], (const float*)d_in[10],
              nullptr, 1, 1, 1);
    // layer 2: g_act1 -> d_out (no planes needed)
    run_layer(nullptr, 1, 0,
              (const float*)d_in[11], (const float*)d_in[12], (const float*)d_in[13],
              (const float*)d_in[14], (const float*)d_in[15],
              (float*)d_out, 2, 0, 0);
}

// round 12
// speedup vs baseline: 1.0815x; 1.0815x over previous
#include <cuda_runtime.h>
#include <cuda_bf16.h>
#include <cstdint>

// Problem constants
#define Bsz 8192
#define Din 1024
#define Rk  64

// ---------------------------------------------------------------------------
// Scratch (__device__ globals; cudaMalloc forbidden)
// ---------------------------------------------------------------------------
__device__ float g_u[Bsz * Rk];          // 2 MB
__device__ float g_h[Bsz * Rk];          // 2 MB
__device__ float g_act0[Bsz * Din];      // 32 MB
__device__ float g_act1[Bsz * Din];      // 32 MB
__device__ float g_Vx[Din * 128];        // 512 KB  [V | (bm@V^T)^T]
// bf16 hi/lo planes (A refreshed per layer, B from weights per layer)
__device__ __align__(16) __nv_bfloat16 g_Ah[(size_t)Bsz * Din];   // 16 MB
__device__ __align__(16) __nv_bfloat16 g_Al[(size_t)Bsz * Din];   // 16 MB
__device__ __align__(16) __nv_bfloat16 g_Bh[(size_t)4096 * Din];  // 8 MB
__device__ __align__(16) __nv_bfloat16 g_Bl[(size_t)4096 * Din];  // 8 MB

__device__ __forceinline__ const float* in_sel(const float* ext, int sel) {
    if (sel == 0) return g_act0;
    if (sel == 1) return g_act1;
    return ext;
}
__device__ __forceinline__ float* out_sel(float* ext, int sel) {
    if (sel == 0) return g_act0;
    if (sel == 1) return g_act1;
    return ext;
}

// ---------------------------------------------------------------------------
// PTX helpers (baseline PTX only — harness targets plain sm_103)
// ---------------------------------------------------------------------------
__device__ __forceinline__ uint32_t smem_u32(const void* p) {
    uint32_t a;
    asm("{ .reg .u64 t; cvta.to.shared.u64 t, %1; cvt.u32.u64 %0, t; }"
        : "=r"(a) : "l"(p));
    return a;
}
#define CPASYNC16(saddr, gptr) \
    asm volatile("cp.async.cg.shared.global [%0], [%1], 16;" \
                 :: "r"(saddr), "l"(gptr) : "memory")
#define CP_COMMIT() asm volatile("cp.async.commit_group;" ::: "memory")
#define CP_WAIT1()  asm volatile("cp.async.wait_group 1;" ::: "memory")

#define LDM4(r, addr) \
    asm volatile("ldmatrix.sync.aligned.m8n8.x4.shared.b16 {%0,%1,%2,%3}, [%4];" \
                 : "=r"((r)[0]), "=r"((r)[1]), "=r"((r)[2]), "=r"((r)[3]) \
                 : "r"(addr))

#define MMA16816(d, a, b) \
    asm volatile("mma.sync.aligned.m16n8k16.row.col.f32.bf16.bf16.f32 " \
                 "{%0,%1,%2,%3}, {%4,%5,%6,%7}, {%8,%9}, {%0,%1,%2,%3};" \
                 : "+f"((d)[0]), "+f"((d)[1]), "+f"((d)[2]), "+f"((d)[3]) \
                 : "r"((a)[0]), "r"((a)[1]), "r"((a)[2]), "r"((a)[3]), \
                   "r"((b)[0]), "r"((b)[1]))

// ---------------------------------------------------------------------------
// Shared-memory layout of the MMA kernel (bytes). Pitch 144 B (16-aligned;
// ldmatrix 8-row offsets mod 128 = {0,16,...112} -> conflict-free).
// Stage: A_H 256x144 | A_L | B_H 128x144 | B_L = 110592 B; 2 stages.
// ---------------------------------------------------------------------------
#define ST_A_H   0
#define ST_A_L   36864
#define ST_B_H   73728
#define ST_B_L   92160
#define ST_BYTES 110592
#define OFF_UF   221184          // u staging: 512 floats = 2048 B
#define SMEM_MMA 223232

// ---------------------------------------------------------------------------
// zero g_h and g_u
// ---------------------------------------------------------------------------
__global__ void zero_kernel() {
    int i = blockIdx.x * 256 + threadIdx.x;
    reinterpret_cast<float4*>(g_h)[i] = make_float4(0.f, 0.f, 0.f, 0.f);
    reinterpret_cast<float4*>(g_u)[i] = make_float4(0.f, 0.f, 0.f, 0.f);
}

// ---------------------------------------------------------------------------
// g_Vx[o][0:64] = V[o][:],  g_Vx[o][64+r] = sum_s bm[r*64+s] * V[o][s]
// ---------------------------------------------------------------------------
__global__ __launch_bounds__(128)
void w2v_kernel(const float* __restrict__ V, const float* __restrict__ bm) {
    __shared__ float Vrow[64];
    __shared__ float bms[4096];
    const int o = blockIdx.x, t = threadIdx.x;
    for (int j = t; j < 4096; j += 128) bms[j] = bm[j];
    if (t < 64) Vrow[t] = V[o * 64 + t];
    __syncthreads();
    if (t < 64) {
        g_Vx[o * 128 + t] = Vrow[t];
    } else {
        const int r = t - 64;
        float s = 0.f;
#pragma unroll
        for (int ss = 0; ss < 64; ++ss) s = fmaf(bms[r * 64 + ss], Vrow[ss], s);
        g_Vx[o * 128 + 64 + r] = s;
    }
}

// ---------------------------------------------------------------------------
// Conversion: fp32 -> bf16 hi/lo planes (elementwise).
// ---------------------------------------------------------------------------
__global__ __launch_bounds__(256)
void conv_kernel(const float* __restrict__ Sext, int sel, int is_b) {
    const float* S = in_sel(Sext, sel);
    __nv_bfloat16* H = is_b ? g_Bh : g_Ah;
    __nv_bfloat16* L = is_b ? g_Bl : g_Al;
    size_t i4 = (size_t)blockIdx.x * 256 + threadIdx.x;
    float4 v = reinterpret_cast<const float4*>(S)[i4];
    __nv_bfloat16 h0 = __float2bfloat16_rn(v.x), h1 = __float2bfloat16_rn(v.y);
    __nv_bfloat16 h2 = __float2bfloat16_rn(v.z), h3 = __float2bfloat16_rn(v.w);
    __nv_bfloat162 lo01 = __floats2bfloat162_rn(v.x - __bfloat162float(h0),
                                                v.y - __bfloat162float(h1));
    __nv_bfloat162 lo23 = __floats2bfloat162_rn(v.z - __bfloat162float(h2),
                                                v.w - __bfloat162float(h3));
    uint2 hp, lp;
    hp.x = (uint32_t)__bfloat16_as_ushort(h0) | ((uint32_t)__bfloat16_as_ushort(h1) << 16);
    hp.y = (uint32_t)__bfloat16_as_ushort(h2) | ((uint32_t)__bfloat16_as_ushort(h3) << 16);
    lp.x = *reinterpret_cast<uint32_t*>(&lo01);
    lp.y = *reinterpret_cast<uint32_t*>(&lo23);
    *reinterpret_cast<uint2*>(H + 4 * i4) = hp;
    *reinterpret_cast<uint2*>(L + 4 * i4) = lp;
}

// ---------------------------------------------------------------------------
// u = X @ U^T (exact fp32), k-partitioned 8 ways with atomic reduce.
// grid (128 m-tiles of 64 rows, 8 k-slices of 128), 256 threads.
// Inner loop fully vectorized: 2x LDS.128 per 16 FMA.
// ---------------------------------------------------------------------------
__global__ __launch_bounds__(256, 2)
void u_kernel(const float* __restrict__ Xext, int xsel, const float* __restrict__ U) {
    const float* X = in_sel(Xext, xsel);
    __shared__ float sb[4352];
    const int tid = threadIdx.x;
    const int m0 = blockIdx.x * 64;
    const int kb = blockIdx.y * 128;
    const int tx = tid & 15, ty = tid >> 4;

    float acc[4][4] = {};
    for (int k0 = kb; k0 < kb + 128; k0 += 32) {
#pragma unroll
        for (int it = 0; it < 2; ++it) {
            int t = tid + it * 256;
            int row = t >> 3, quad = t & 7;
            float4 v = *reinterpret_cast<const float4*>(
                X + (size_t)(m0 + row) * Din + k0 + quad * 4);
            sb[(quad * 4 + 0) * 68 + row] = v.x;
            sb[(quad * 4 + 1) * 68 + row] = v.y;
            sb[(quad * 4 + 2) * 68 + row] = v.z;
            sb[(quad * 4 + 3) * 68 + row] = v.w;
            float4 w = *reinterpret_cast<const float4*>(
                U + (size_t)row * Din + k0 + quad * 4);
            sb[2176 + (quad * 4 + 0) * 68 + row] = w.x;
            sb[2176 + (quad * 4 + 1) * 68 + row] = w.y;
            sb[2176 + (quad * 4 + 2) * 68 + row] = w.z;
            sb[2176 + (quad * 4 + 3) * 68 + row] = w.w;
        }
        __syncthreads();
#pragma unroll
        for (int k = 0; k < 32; ++k) {
            float4 a4 = *reinterpret_cast<const float4*>(sb + k * 68 + ty * 4);
            float4 b4 = *reinterpret_cast<const float4*>(sb + 2176 + k * 68 + tx * 4);
            float a[4] = {a4.x, a4.y, a4.z, a4.w};
            float b[4] = {b4.x, b4.y, b4.z, b4.w};
#pragma unroll
            for (int i = 0; i < 4; ++i)
#pragma unroll
                for (int j = 0; j < 4; ++j) acc[i][j] = fmaf(a[i], b[j], acc[i][j]);
        }
        __syncthreads();
    }
#pragma unroll
    for (int i = 0; i < 4; ++i)
#pragma unroll
        for (int j = 0; j < 4; ++j)
            atomicAdd(&g_u[(size_t)(m0 + ty * 4 + i) * Rk + tx * 4 + j], acc[i][j]);
}

// ---------------------------------------------------------------------------
// Main GEMM: C = X @ Wm^T (bf16 3-term HMMA) + fused einsum epilogue.
// CTA M=256 x N=128, 512 threads (warp grid 4x4, warp tile 64x32).
// k-chunk 64, 2-stage cp.async pipeline (R5-proven config).
// grid = (32 nb, 32 mb).
// ---------------------------------------------------------------------------
__global__ __launch_bounds__(512, 1)
void apg_mma_kernel() {
    extern __shared__ __align__(16) char sm[];
    const int t = threadIdx.x, lane = t & 31, w = t >> 5;
    const int mw = w >> 2, nw = w & 3;
    const int nb = blockIdx.x, mb = blockIdx.y;
    const int m0 = mb * 256, n0 = nb * 128;
    const uint32_t smb = smem_u32(sm);

    const __nv_bfloat16* gAh = g_Ah + (size_t)m0 * Din;
    const __nv_bfloat16* gAl = g_Al + (size_t)m0 * Din;
    const __nv_bfloat16* gBh = g_Bh + (size_t)n0 * Din;
    const __nv_bfloat16* gBl = g_Bl + (size_t)n0 * Din;

    auto issue = [&](int kc, int stg) {
        uint32_t sb0 = smb + stg * ST_BYTES;
        const size_t ko = (size_t)kc * 64;
#pragma unroll
        for (int i = 0; i < 4; ++i) {
            int idx = t + i * 512, row = idx >> 3, grp = idx & 7;
            CPASYNC16(sb0 + ST_A_H + row * 144 + grp * 16, gAh + (size_t)row * Din + ko + grp * 8);
            CPASYNC16(sb0 + ST_A_L + row * 144 + grp * 16, gAl + (size_t)row * Din + ko + grp * 8);
        }
#pragma unroll
        for (int i = 0; i < 2; ++i) {
            int idx = t + i * 512, row = idx >> 3, grp = idx & 7;
            CPASYNC16(sb0 + ST_B_H + row * 144 + grp * 16, gBh + (size_t)row * Din + ko + grp * 8);
            CPASYNC16(sb0 + ST_B_L + row * 144 + grp * 16, gBl + (size_t)row * Din + ko + grp * 8);
        }
    };

    // u staging (overlaps with prologue load)
    issue(0, 0);
    CP_COMMIT();
    {
        float* uf = reinterpret_cast<float*>(sm + OFF_UF);
        uf[t] = g_u[(size_t)(m0 + (t >> 1)) * Rk + 2 * nb + (t & 1)];
    }

    float acc[4][4][4];
#pragma unroll
    for (int i = 0; i < 4; ++i)
#pragma unroll
        for (int j = 0; j < 4; ++j)
#pragma unroll
            for (int e = 0; e < 4; ++e) acc[i][j][e] = 0.f;

    const int arow = lane & 15, acol = (lane >> 4) * 8;
    const int brow = ((lane >> 4) << 3) + (lane & 7), bcol = ((lane >> 3) & 1) * 8;
    const uint32_t aoff = ((mw * 64 + arow) * 72 + acol) * 2;
    const uint32_t boff = ((nw * 32 + brow) * 72 + bcol) * 2;

    for (int i = 0; i < 16; ++i) {
        if (i < 15) issue(i + 1, (i + 1) & 1);
        CP_COMMIT();
        CP_WAIT1();
        __syncthreads();                       // chunk i staged

        const uint32_t base = smb + (i & 1) * ST_BYTES;
#pragma unroll
        for (int ks = 0; ks < 4; ++ks) {
            uint32_t ah[4][4], al[4][4];
#pragma unroll
            for (int mt = 0; mt < 4; ++mt) {
                uint32_t aa = base + ST_A_H + aoff + mt * (16 * 144) + ks * 32;
                LDM4(ah[mt], aa);
                LDM4(al[mt], aa + (ST_A_L - ST_A_H));
            }
#pragma unroll
            for (int p = 0; p < 2; ++p) {
                uint32_t bb = base + ST_B_H + boff + p * (16 * 144) + ks * 32;
                uint32_t bh4[4], bl4[4];
                LDM4(bh4, bb);
                LDM4(bl4, bb + (ST_B_L - ST_B_H));
                uint32_t b0h[2] = {bh4[0], bh4[1]}, b1h[2] = {bh4[2], bh4[3]};
                uint32_t b0l[2] = {bl4[0], bl4[1]}, b1l[2] = {bl4[2], bl4[3]};
#pragma unroll
                for (int mt = 0; mt < 4; ++mt) {
                    MMA16816(acc[mt][2 * p], ah[mt], b0h);
                    MMA16816(acc[mt][2 * p], ah[mt], b0l);
                    MMA16816(acc[mt][2 * p], al[mt], b0h);
                    MMA16816(acc[mt][2 * p + 1], ah[mt], b1h);
                    MMA16816(acc[mt][2 * p + 1], ah[mt], b1l);
                    MMA16816(acc[mt][2 * p + 1], al[mt], b1h);
                }
            }
        }
        __syncthreads();                       // all warps done with stage i&1
    }

    // ---- fused einsum epilogue ----
    float* hp = reinterpret_cast<float*>(sm);              // 256 x 65 floats
    const float* uf = reinterpret_cast<const float*>(sm + OFF_UF);
    const int mbase = mw * 64, scol = (nw & 1) * 32;
    if (nw < 2) {    // cols 0..63 -> r = 2nb (u0)
#pragma unroll
        for (int mt = 0; mt < 4; ++mt)
#pragma unroll
            for (int nt = 0; nt < 4; ++nt) {
                int m0r = mbase + mt * 16 + (lane >> 2);
                int s0 = scol + nt * 8 + 2 * (lane & 3);
                hp[m0r * 65 + s0]           = acc[mt][nt][0] * uf[m0r * 2];
                hp[m0r * 65 + s0 + 1]       = acc[mt][nt][1] * uf[m0r * 2];
                hp[(m0r + 8) * 65 + s0]     = acc[mt][nt][2] * uf[(m0r + 8) * 2];
                hp[(m0r + 8) * 65 + s0 + 1] = acc[mt][nt][3] * uf[(m0r + 8) * 2];
            }
    }
    __syncthreads();
    if (nw >= 2) {   // cols 64..127 -> r = 2nb+1 (u1)
#pragma unroll
        for (int mt = 0; mt < 4; ++mt)
#pragma unroll
            for (int nt = 0; nt < 4; ++nt) {
                int m0r = mbase + mt * 16 + (lane >> 2);
                int s0 = scol + nt * 8 + 2 * (lane & 3);
                hp[m0r * 65 + s0]           += acc[mt][nt][0] * uf[m0r * 2 + 1];
                hp[m0r * 65 + s0 + 1]       += acc[mt][nt][1] * uf[m0r * 2 + 1];
                hp[(m0r + 8) * 65 + s0]     += acc[mt][nt][2] * uf[(m0r + 8) * 2 + 1];
                hp[(m0r + 8) * 65 + s0 + 1] += acc[mt][nt][3] * uf[(m0r + 8) * 2 + 1];
            }
    }
    __syncthreads();

    float* dst = g_h + (size_t)m0 * Rk;
#pragma unroll 8
    for (int ii = 0; ii < 32; ++ii) {
        int idx = ii * 512 + t;               // m = idx>>6, s = idx&63
        atomicAdd(dst + idx, hp[(idx >> 6) * 65 + (idx & 63)]);
    }
}

// ---------------------------------------------------------------------------
// out = [h | u] @ [V | W2]^T + b (+ReLU). Optionally also emits bf16 hi/lo
// planes of the activation (feeds next layer's GEMM).
// K=128. grid (8, 64), 256 thr.
// ---------------------------------------------------------------------------
__global__ __launch_bounds__(256, 2)
void apg_out_kernel(const float* __restrict__ bias,
                    float* __restrict__ Oext, int osel, int relu, int planes) {
    float* O = out_sel(Oext, osel);
    __shared__ float sb[8448];
    const int tid = threadIdx.x;
    const int m0 = blockIdx.y * 128;
    const int n0 = blockIdx.x * 128;
    const int tx = tid & 15, ty = tid >> 4;

    float acc[8][8] = {};
    for (int k0 = 0; k0 < 128; k0 += 32) {
        const float* Asrc = (k0 < 64) ? g_h : g_u;
        const int kk = k0 & 63;
#pragma unroll
        for (int it = 0; it < 4; ++it) {
            int t = tid + it * 256;
            int row = t >> 3, quad = t & 7;
            float4 v = *reinterpret_cast<const float4*>(
                Asrc + (size_t)(m0 + row) * Rk + kk + quad * 4);
            sb[(quad * 4 + 0) * 132 + row] = v.x;
            sb[(quad * 4 + 1) * 132 + row] = v.y;
            sb[(quad * 4 + 2) * 132 + row] = v.z;
            sb[(quad * 4 + 3) * 132 + row] = v.w;
            float4 wv = *reinterpret_cast<const float4*>(
                g_Vx + (size_t)(n0 + row) * 128 + k0 + quad * 4);
            sb[4224 + (quad * 4 + 0) * 132 + row] = wv.x;
            sb[4224 + (quad * 4 + 1) * 132 + row] = wv.y;
            sb[4224 + (quad * 4 + 2) * 132 + row] = wv.z;
            sb[4224 + (quad * 4 + 3) * 132 + row] = wv.w;
        }
        __syncthreads();
#pragma unroll
        for (int k = 0; k < 32; ++k) {
            float a[8], b[8];
            float4 a0 = *reinterpret_cast<const float4*>(sb + k * 132 + ty * 8);
            float4 a1 = *reinterpret_cast<const float4*>(sb + k * 132 + ty * 8 + 4);
            float4 b0 = *reinterpret_cast<const float4*>(sb + 4224 + k * 132 + tx * 8);
            float4 b1 = *reinterpret_cast<const float4*>(sb + 4224 + k * 132 + tx * 8 + 4);
            a[0] = a0.x; a[1] = a0.y; a[2] = a0.z; a[3] = a0.w;
            a[4] = a1.x; a[5] = a1.y; a[6] = a1.z; a[7] = a1.w;
            b[0] = b0.x; b[1] = b0.y; b[2] = b0.z; b[3] = b0.w;
            b[4] = b1.x; b[5] = b1.y; b[6] = b1.z; b[7] = b1.w;
#pragma unroll
            for (int i = 0; i < 8; ++i)
#pragma unroll
                for (int j = 0; j < 8; ++j) acc[i][j] += a[i] * b[j];
        }
        __syncthreads();
    }

    float4 bv0 = *reinterpret_cast<const float4*>(bias + n0 + tx * 8);
    float4 bv1 = *reinterpret_cast<const float4*>(bias + n0 + tx * 8 + 4);
    float bb[8] = {bv0.x, bv0.y, bv0.z, bv0.w, bv1.x, bv1.y, bv1.z, bv1.w};
#pragma unroll
    for (int i = 0; i < 8; ++i) {
        float v[8];
#pragma unroll
        for (int j = 0; j < 8; ++j) {
            v[j] = acc[i][j] + bb[j];
            if (relu) v[j] = fmaxf(v[j], 0.0f);
        }
        size_t base = (size_t)(m0 + ty * 8 + i) * Din + n0 + tx * 8;
        float4* dst = reinterpret_cast<float4*>(O + base);
        dst[0] = make_float4(v[0], v[1], v[2], v[3]);
        dst[1] = make_float4(v[4], v[5], v[6], v[7]);
        if (planes) {
            uint2 hpk[2], lpk[2];
#pragma unroll
            for (int q = 0; q < 2; ++q) {
                __nv_bfloat16 h0 = __float2bfloat16_rn(v[4 * q + 0]);
                __nv_bfloat16 h1 = __float2bfloat16_rn(v[4 * q + 1]);
                __nv_bfloat16 h2 = __float2bfloat16_rn(v[4 * q + 2]);
                __nv_bfloat16 h3 = __float2bfloat16_rn(v[4 * q + 3]);
                __nv_bfloat162 l01 = __floats2bfloat162_rn(
                    v[4 * q + 0] - __bfloat162float(h0),
                    v[4 * q + 1] - __bfloat162float(h1));
                __nv_bfloat162 l23 = __floats2bfloat162_rn(
                    v[4 * q + 2] - __bfloat162float(h2),
                    v[4 * q + 3] - __bfloat162float(h3));
                hpk[q].x = (uint32_t)__bfloat16_as_ushort(h0) |
                           ((uint32_t)__bfloat16_as_ushort(h1) << 16);
                hpk[q].y = (uint32_t)__bfloat16_as_ushort(h2) |
                           ((uint32_t)__bfloat16_as_ushort(h3) << 16);
                lpk[q].x = *reinterpret_cast<uint32_t*>(&l01);
                lpk[q].y = *reinterpret_cast<uint32_t*>(&l23);
            }
            *reinterpret_cast<uint4*>(g_Ah + base) =
                make_uint4(hpk[0].x, hpk[0].y, hpk[1].x, hpk[1].y);
            *reinterpret_cast<uint4*>(g_Al + base) =
                make_uint4(lpk[0].x, lpk[0].y, lpk[1].x, lpk[1].y);
        }
    }
}

// ---------------------------------------------------------------------------
// Launch
// ---------------------------------------------------------------------------
static void run_layer(const float* xext, int xsel, int need_conv,
                      const float* Wm, const float* bm, const float* U,
                      const float* V, const float* bias,
                      float* oext, int osel, int relu, int planes) {
    zero_kernel<<<512, 256>>>();
    w2v_kernel<<<Din, 128>>>(V, bm);
    if (need_conv) conv_kernel<<<8192, 256>>>(xext, xsel, 0);  // x -> A planes
    conv_kernel<<<4096, 256>>>(Wm, 2, 1);                      // Wm -> B planes
    u_kernel<<<dim3(128, 8), 256>>>(xext, xsel, U);
    apg_mma_kernel<<<dim3(32, 32), 512, SMEM_MMA>>>();
    apg_out_kernel<<<dim3(8, 64), 256>>>(bias, oext, osel, relu, planes);
}

extern "C" void kernel_launch(void* const* d_in, const int* in_sizes, int n_in,
                              void* d_out, int out_size) {
    cudaFuncSetAttribute(apg_mma_kernel,
                         cudaFuncAttributeMaxDynamicSharedMemorySize, SMEM_MMA);
    const float* x = (const float*)d_in[0];
    // layer 0: x -> g_act0 (+ planes for layer 1)
    run_layer(x, 2, 1,
              (const float*)d_in[1], (const float*)d_in[2], (const float*)d_in[3],
              (const float*)d_in[4], (const float*)d_in[5],
              nullptr, 0, 1, 1);
    // layer 1: g_act0 -> g_act1 (+ planes for layer 2)
    run_layer(nullptr, 0, 0,
              (const float*)d_in[6], (const float*)d_in[7], (const float*)d_in[8],
              (const float*)d_in[9], (const float*)d_in[10],
              nullptr, 1, 1, 1);
    // layer 2: g_act1 -> d_out (no planes needed)
    run_layer(nullptr, 1, 0,
              (const float*)d_in[11], (const float*)d_in[12], (const float*)d_in[13],
              (const float*)d_in[14], (const float*)d_in[15],
              (float*)d_out, 2, 0, 0);
}